// round 16
// baseline (speedup 1.0000x reference)
#include <cuda_runtime.h>
#include <math.h>

#define ZNUM  64
#define CELLS 64
#define C1    64
#define C2    32
#define BMAX  64

typedef unsigned long long ull;

// ---------- helpers ----------

__device__ __forceinline__ int read_dim(const void* p) {
    int   iv = ((const int*)p)[0];
    float fv = ((const float*)p)[0];
    bool int_ok = (iv >= 8 && iv <= 1000000);
    if (!int_ok && fv >= 8.f && fv <= 1.0e6f && floorf(fv) == fv) return (int)fv;
    return iv;
}

__device__ __forceinline__ void ffma2(ull& d, ull a, ull b) {
    asm("fma.rn.f32x2 %0, %1, %2, %0;" : "+l"(d) : "l"(a), "l"(b));
}
__device__ __forceinline__ void fadd2(ull& d, ull a) {
    asm("add.rn.f32x2 %0, %0, %1;" : "+l"(d) : "l"(a));
}
__device__ __forceinline__ ull pack2(float v) {
    ull r;
    asm("mov.b64 %0, {%1, %1};" : "=l"(r) : "f"(v));
    return r;
}

// ---------- fused kernel ----------
// grid (2, B) = 128 blocks (one wave). 512 threads = 16 warps.
// Warp-specialized prologue (no block barrier before the join):
//   warps 0-1 : mask layout vote (warp-local) + zone data -> smem
//   warps 2-7 : stage w1/b1/b2 -> smem
//   warps 8-15: weight LDGs at cycle 0 -> regs -> STS (wpair)
// Then: pooling (warps 0-7, shfl combine) | 1x1 | mainloop | reduce | epilogue.

__global__ __launch_bounds__(512, 1)
void kFused(const float* __restrict__ hist,     // [B,Z,2]
            const void*  __restrict__ maskp,    // [B,Z]
            const int*   __restrict__ fr,       // [B,Z,4]
            const void*  __restrict__ Hp, const void* __restrict__ Wp,
            const float* __restrict__ w1,       // [C1,2]
            const float* __restrict__ b1,       // [C1]
            const float* __restrict__ w2,       // [C2,C1,3,3]
            const float* __restrict__ b2,       // [C2]
            float* __restrict__ out,            // [B,C2,64]
            int nwords)
{
    const int ocg  = blockIdx.x;      // 0..1 -> oc base ocg*16
    const int b    = blockIdx.y;
    const int tid  = threadIdx.x;
    const int lane = tid & 31;

    __shared__ int   s_sy[ZNUM], s_sx[ZNUM], s_ey[ZNUM], s_ex[ZNUM];
    __shared__ float s_mv[ZNUM], s_vv[ZNUM];
    __shared__ int   s_mk[ZNUM];
    __shared__ float s_x[CELLS][2];
    __shared__ float s_w1[2 * C1], s_b1[C1], s_b2[C2];

    extern __shared__ __align__(16) float blob[];   // 57344 B dynamic
    float* hs    = blob;                 // [ic][cell], 16 KB
    float* wpair = blob + 4096;          // [pair][ic][10 ull], 40 KB
    ull*   part  = (ull*)blob;           // [t][pair][cell] ull, 36 KB (alias)

    const int oc0 = ocg * 16;

    int Hv = 0, Wv = 0;
    if (tid < 256) { Hv = read_dim(Hp); Wv = read_dim(Wp); }

    if (tid >= 256) {
        // ---- warps 8-15: weight staging, LDGs fire at cycle 0 ----
        const int stid = tid - 256;          // 0..255, 4 items each
        float v[4][9];
        int pi_[4], si_[4], ici_[4];
#pragma unroll
        for (int k = 0; k < 4; ++k) {
            const int item = stid + (k << 8);
            pi_[k]  = item >> 7;             // 0..7
            si_[k]  = (item >> 6) & 1;
            ici_[k] = item & 63;
            const float* src = w2 + (oc0 + 2 * pi_[k] + si_[k]) * 576 + ici_[k] * 9;
#pragma unroll
            for (int t = 0; t < 9; ++t) v[k][t] = src[t];
        }
#pragma unroll
        for (int k = 0; k < 4; ++k) {
            float* dst = wpair + (pi_[k] * 64 + ici_[k]) * 20 + si_[k];
#pragma unroll
            for (int t = 0; t < 9; ++t) dst[2 * t] = v[k][t];
        }
    } else if (tid >= 64) {
        // ---- warps 2-7: stage small params ----
        const int j = tid - 64;              // 0..191
        if (j < 2 * C1)            s_w1[j] = w1[j];
        else if (j < 2 * C1 + C1)  s_b1[j - 2 * C1] = b1[j - 2 * C1];
        if (j < C2)                s_b2[j] = b2[j];
    } else {
        // ---- warps 0-1: mask (warp-local vote) + zone data ----
        const int z = tid;
        // speculative byte-layout mask (always in-bounds)
        const unsigned char mvb = ((const unsigned char*)maskp)[b * ZNUM + z];
        // layout scan: each warp votes over words 0..31 (identical result)
        const unsigned* mw = (const unsigned*)maskp;
        int widx = lane < nwords ? lane : nwords - 1;
        unsigned sw = mw[widx];
        int p_int   = (sw == 0u || sw == 1u);
        int p_float = (sw == 0u || sw == 0x3F800000u);
        // zone box + hist (vector loads, fire early)
        const int4   box = *(const int4*)(fr + ((long)b * ZNUM + z) * 4);
        const float2 hv  = *(const float2*)(hist + ((long)b * ZNUM + z) * 2);

        int all_i = __all_sync(0xffffffffu, p_int);
        int all_f = __all_sync(0xffffffffu, p_float);
        int mk;
        if (all_i)      mk = ((const int*)maskp)[b * ZNUM + z] != 0;
        else if (all_f) mk = ((const float*)maskp)[b * ZNUM + z] != 0.0f;
        else            mk = mvb != 0;

        s_sy[z] = max(box.x, 0);
        s_sx[z] = max(box.y, 0);
        s_ey[z] = min(box.z, Hv);
        s_ex[z] = min(box.w, Wv);
        s_mv[z] = hv.x;
        s_vv[z] = hv.y;
        s_mk[z] = mk;
    }
    __syncthreads();   // A: zone smem + staged params visible

    // ---- pooling: warps 0-7; thread = (cell, zg); shfl combine ----
    const int bh = Hv / 8, bw = Wv / 8;
    if (tid < 256) {
        const float inv_area = 1.0f / (float)(bh * bw);
        const float area = (float)(bh * bw);
        const int cell = tid >> 2;
        const int zg   = tid & 3;
        const int r = cell >> 3, c = cell & 7;
        const int cy0 = r * bh, cy1 = cy0 + bh;
        const int cx0 = c * bw, cx1 = cx0 + bw;

        float sm = 0.f, sv = 0.f;
        int hit = 0, fb = 0;
        for (int z = zg * 16 + 15; z >= zg * 16; --z) {   // LWW within group
            if (!s_mk[z]) continue;
            int iy0 = max(s_sy[z], cy0), iy1 = min(s_ey[z], cy1);
            int ix0 = max(s_sx[z], cx0), ix1 = min(s_ex[z], cx1);
            if (iy0 >= iy1 || ix0 >= ix1) continue;
            if (iy0 == cy0 && iy1 == cy1 && ix0 == cx0 && ix1 == cx1) {
                sm = s_mv[z] * area;
                sv = s_vv[z] * area;
            } else {
                fb = 1;   // partial cover -> exact per-pixel fallback
            }
            hit = 1;
            break;
        }
        unsigned fl = (unsigned)(hit | (fb << 1));
        // gather zg1..3 into the zg0 lane of each 4-lane group
        float sm1 = __shfl_down_sync(0xffffffffu, sm, 1, 4);
        float sv1 = __shfl_down_sync(0xffffffffu, sv, 1, 4);
        unsigned f1 = __shfl_down_sync(0xffffffffu, fl, 1, 4);
        float sm2 = __shfl_down_sync(0xffffffffu, sm, 2, 4);
        float sv2 = __shfl_down_sync(0xffffffffu, sv, 2, 4);
        unsigned f2 = __shfl_down_sync(0xffffffffu, fl, 2, 4);
        float sm3 = __shfl_down_sync(0xffffffffu, sm, 3, 4);
        float sv3 = __shfl_down_sync(0xffffffffu, sv, 3, 4);
        unsigned f3 = __shfl_down_sync(0xffffffffu, fl, 3, 4);

        if (zg == 0) {
            float csm = sm, csv = sv; unsigned cfl = fl;
            if (f3 & 1u)      { csm = sm3; csv = sv3; cfl = f3; }
            else if (f2 & 1u) { csm = sm2; csv = sv2; cfl = f2; }
            else if (f1 & 1u) { csm = sm1; csv = sv1; cfl = f1; }
            if (cfl & 2u) {                       // exact per-pixel fallback
                csm = 0.f; csv = 0.f;
                for (int y = cy0; y < cy1; ++y)
                    for (int x = cx0; x < cx1; ++x)
                        for (int z = ZNUM - 1; z >= 0; --z) {
                            if (!s_mk[z]) continue;
                            if (y >= s_sy[z] && y < s_ey[z] &&
                                x >= s_sx[z] && x < s_ex[z]) {
                                csm += s_mv[z]; csv += s_vv[z];
                                break;
                            }
                        }
            }
            float tm = csm * inv_area, tv = csv * inv_area;
            s_x[cell][0] = log1pf(fmaxf(tm, 0.f));
            s_x[cell][1] = log1pf(fmaxf(tv, 0.f));
        }
    }
    __syncthreads();   // B: s_x ready

    // ---- 1x1 conv (2 -> C1) + SiLU into hs (params from smem) ----
#pragma unroll
    for (int k = 0; k < 8; ++k) {
        const int i = tid + k * 512;
        const int ch = i >> 6, cell = i & 63;
        float v = fmaf(s_w1[ch * 2 + 0], s_x[cell][0],
                  fmaf(s_w1[ch * 2 + 1], s_x[cell][1], s_b1[ch]));
        hs[i] = v * __fdividef(1.0f, 1.0f + __expf(-v));
    }
    __syncthreads();   // C: hs + wpair ready

    // ---- mainloop: 9-tap GEMM over 32 ic per warp, software-pipelined ----
    const int w      = tid >> 5;
    const int pair   = w & 7;
    const int ichalf = w >> 3;

    ull a0[9], a1[9];
#pragma unroll
    for (int t = 0; t < 9; ++t) { a0[t] = 0; a1[t] = 0; }

    {
        const int    icb = ichalf * 32;
        const float* hp  = hs + icb * 64 + lane;
        const float* qp  = wpair + pair * 1280 + icb * 20;

        float h0a = hp[0],  h1a = hp[32];
        float h0b = hp[64], h1b = hp[96];
        ulonglong2 w01 = *(const ulonglong2*)(qp);
        ulonglong2 w23 = *(const ulonglong2*)(qp + 4);
        ulonglong2 w45 = *(const ulonglong2*)(qp + 8);
        ulonglong2 w67 = *(const ulonglong2*)(qp + 12);
        ull        w8  = *(const ull*)(qp + 16);

#pragma unroll
        for (int ii = 0; ii < 32; ++ii) {
            const ull H0 = pack2(h0a);
            const ull H1 = pack2(h1a);
            const ulonglong2 c01 = w01, c23 = w23, c45 = w45, c67 = w67;
            const ull        c8  = w8;
            h0a = h0b; h1a = h1b;
            if (ii < 30) {
                h0b = hp[(ii + 2) * 64];
                h1b = hp[(ii + 2) * 64 + 32];
            }
            if (ii < 31) {
                const float* qn = qp + (ii + 1) * 20;
                w01 = *(const ulonglong2*)(qn);
                w23 = *(const ulonglong2*)(qn + 4);
                w45 = *(const ulonglong2*)(qn + 8);
                w67 = *(const ulonglong2*)(qn + 12);
                w8  = *(const ull*)(qn + 16);
            }
            ffma2(a0[0], c01.x, H0);  ffma2(a1[0], c01.x, H1);
            ffma2(a0[1], c01.y, H0);  ffma2(a1[1], c01.y, H1);
            ffma2(a0[2], c23.x, H0);  ffma2(a1[2], c23.x, H1);
            ffma2(a0[3], c23.y, H0);  ffma2(a1[3], c23.y, H1);
            ffma2(a0[4], c45.x, H0);  ffma2(a1[4], c45.x, H1);
            ffma2(a0[5], c45.y, H0);  ffma2(a1[5], c45.y, H1);
            ffma2(a0[6], c67.x, H0);  ffma2(a1[6], c67.x, H1);
            ffma2(a0[7], c67.y, H0);  ffma2(a1[7], c67.y, H1);
            ffma2(a0[8], c8,    H0);  ffma2(a1[8], c8,    H1);
        }
    }

    __syncthreads();   // D: wpair reads done -> part may alias

    // ---- 2 -> 1 reduction ----
    if (ichalf == 1) {
#pragma unroll
        for (int t = 0; t < 9; ++t) {
            ull* dst = part + (t * 8 + pair) * 64;
            dst[lane]      = a0[t];
            dst[32 + lane] = a1[t];
        }
    }
    __syncthreads();   // E
    if (ichalf == 0) {
#pragma unroll
        for (int t = 0; t < 9; ++t) {
            ull* dst = part + (t * 8 + pair) * 64;
            fadd2(a0[t], dst[lane]);
            fadd2(a1[t], dst[32 + lane]);
            dst[lane]      = a0[t];
            dst[32 + lane] = a1[t];
        }
    }
    __syncthreads();   // F

    // ---- epilogue: 9-tap shift-add; 2 outputs per thread ----
    {
        const float* U = (const float*)part;
#pragma unroll
        for (int r = 0; r < 2; ++r) {
            const int j    = tid + r * 512;      // 0..1023
            const int oc_l = j >> 6;             // 0..15
            const int cell = j & 63;
            const int pr   = oc_l >> 1;
            const int s    = oc_l & 1;
            const int y = cell >> 3, x = cell & 7;
            float sum = s_b2[oc0 + oc_l];
#pragma unroll
            for (int t = 0; t < 9; ++t) {
                const int yy = y + t / 3 - 1;
                const int xx = x + t % 3 - 1;
                if (yy >= 0 && yy < 8 && xx >= 0 && xx < 8)
                    sum += U[((t * 8 + pr) * 64 + yy * 8 + xx) * 2 + s];
            }
            out[((long)b * C2 + oc0 + oc_l) * 64 + cell] = sum;
        }
    }
}

// ---------- launch ----------

#define DYN_SMEM 57344

extern "C" void kernel_launch(void* const* d_in, const int* in_sizes, int n_in,
                              void* d_out, int out_size)
{
    // input order: hist_BZ2, mask_BZ, fr_BZ4, H, W, w1, b1, w2, b2
    const float* hist  = (const float*)d_in[0];
    const void*  maskp = d_in[1];
    const int*   fr    = (const int*)d_in[2];
    const void*  Hp    = d_in[3];
    const void*  Wp    = d_in[4];
    const float* w1    = (const float*)d_in[5];
    const float* b1    = (const float*)d_in[6];
    const float* w2    = (const float*)d_in[7];
    const float* b2    = (const float*)d_in[8];
    float* out = (float*)d_out;

    int B = in_sizes[1] / ZNUM;
    if (B < 1) B = 1;
    if (B > BMAX) B = BMAX;

    int nwords = in_sizes[1] / 4;
    if (nwords > 256) nwords = 256;
    if (nwords < 1) nwords = 1;

    cudaFuncSetAttribute(kFused, cudaFuncAttributeMaxDynamicSharedMemorySize,
                         DYN_SMEM);

    kFused<<<dim3(2, B), 512, DYN_SMEM>>>(hist, maskp, fr, Hp, Wp,
                                          w1, b1, w2, b2, out, nwords);
}